// round 15
// baseline (speedup 1.0000x reference)
#include <cuda_runtime.h>
#include <cuda_fp16.h>
#include <cstdint>
#include <math.h>

#define BDIM 128
#define RDIM 36
#define WDIM 64
#define DDIM 1024
#define TRI_LEN 720   // packed padded upper-triangular Gram floats per image

// ---------------- device globals (no runtime allocation; zero-initialized) --
__device__ __align__(128) float g_C[(size_t)BDIM * RDIM * BDIM * WDIM];   // [4608][8192]
__device__ __align__(128) __half g_A[(size_t)BDIM * RDIM * DDIM];         // fp16(im)
__device__ __align__(128) __half g_B[(size_t)BDIM * WDIM * DDIM];         // fp16(s)
__device__ __align__(16) float g_tri[BDIM * TRI_LEN];                      // packed Gram
__device__ float g_ncap[BDIM * WDIM];
__device__ float g_scores[BDIM * BDIM];

// row r of the packed triangular Gram starts at OFF[r], width ((39-r)&~3)
__constant__ int c_OFF[RDIM] = {
    0, 36, 72, 108, 144, 176, 208, 240, 272, 300, 328, 356,
    384, 408, 432, 456, 480, 500, 520, 540, 560, 576, 592, 608,
    624, 636, 648, 660, 672, 680, 688, 696, 704, 708, 712, 716};

// ---------------- PTX helpers (baseline compute_103-safe only) ----------------
__device__ __forceinline__ unsigned su32(const void* p) {
    unsigned a;
    asm("{ .reg .u64 t; cvta.to.shared.u64 t, %1; cvt.u32.u64 %0, t; }" : "=r"(a) : "l"(p));
    return a;
}
__device__ __forceinline__ void cpa16_s(unsigned dst, const void* src) {
    asm volatile("cp.async.cg.shared.global [%0], [%1], 16;" :: "r"(dst), "l"(src));
}
__device__ __forceinline__ void cp_commit() { asm volatile("cp.async.commit_group;"); }

#define LDSM4(r, addr) \
    asm volatile("ldmatrix.sync.aligned.m8n8.x4.shared.b16 {%0,%1,%2,%3}, [%4];" \
                 : "=r"((r)[0]), "=r"((r)[1]), "=r"((r)[2]), "=r"((r)[3]) : "r"(addr))

#define MMAF16(d, a, b0v, b1v) \
    asm volatile("mma.sync.aligned.m16n8k16.row.col.f32.f16.f16.f32 " \
                 "{%0,%1,%2,%3}, {%4,%5,%6,%7}, {%8,%9}, {%0,%1,%2,%3};" \
                 : "+f"((d)[0]), "+f"((d)[1]), "+f"((d)[2]), "+f"((d)[3]) \
                 : "r"((a)[0]), "r"((a)[1]), "r"((a)[2]), "r"((a)[3]), "r"(b0v), "r"(b1v))

// ============================================================================
// Converts. Device globals referenced DIRECTLY in device code (host-side
// symbol decay -> host shadow; GB300 ATS accepts it silently).
// ============================================================================
__global__ void __launch_bounds__(256) convert_im_kernel(const float* __restrict__ im) {
    int i = blockIdx.x * 256 + threadIdx.x;                 // over float4s
    if (i >= BDIM * RDIM * DDIM / 4) return;
    float4 x = ((const float4*)im)[i];
    __half2* ap = (__half2*)g_A;
    ap[2 * i]     = __half2(__float2half_rn(x.x), __float2half_rn(x.y));
    ap[2 * i + 1] = __half2(__float2half_rn(x.z), __float2half_rn(x.w));
}

// convert_s merged with ncap: one block per caption-word row (8192 rows)
__global__ void __launch_bounds__(256) convs_ncap_kernel(const float* __restrict__ s) {
    const int row = blockIdx.x;            // 0..8191
    const int t = threadIdx.x;
    const int warp = t >> 5, lane = t & 31;
    __shared__ float ws[8];

    float4 x = ((const float4*)(s + (size_t)row * DDIM))[t];
    __half2* bp = (__half2*)(g_B + (size_t)row * DDIM);
    bp[2 * t]     = __half2(__float2half_rn(x.x), __float2half_rn(x.y));
    bp[2 * t + 1] = __half2(__float2half_rn(x.z), __float2half_rn(x.w));

    float ss = x.x * x.x + x.y * x.y + x.z * x.z + x.w * x.w;
    #pragma unroll
    for (int o = 16; o; o >>= 1) ss += __shfl_down_sync(0xffffffffu, ss, o);
    if (lane == 0) ws[warp] = ss;
    __syncthreads();
    if (t == 0) {
        float tot = 0.f;
        #pragma unroll
        for (int k = 0; k < 8; ++k) tot += ws[k];
        g_ncap[row] = sqrtf(tot);
    }
}

// ============================================================================
// Gram: register-blocked tiled kernel (one CTA per image, 144 threads).
// ============================================================================
#define GSTRIDE 132

__global__ void __launch_bounds__(144) gram_kernel(const float* __restrict__ im) {
    __shared__ __align__(16) float sm[RDIM * GSTRIDE];
    const int i = blockIdx.x;
    const int t = threadIdx.x;
    const int tr = t / 12, tc = t - tr * 12;
    const float* base = im + (size_t)i * RDIM * DDIM;

    for (int idx = t; idx < TRI_LEN; idx += 144) g_tri[i * TRI_LEN + idx] = 0.f;

    float acc[3][3];
    #pragma unroll
    for (int ka = 0; ka < 3; ++ka)
        #pragma unroll
        for (int kb = 0; kb < 3; ++kb) acc[ka][kb] = 0.f;

    for (int ch = 0; ch < 8; ++ch) {
        __syncthreads();
        for (int idx = t; idx < RDIM * 32; idx += 144) {
            int r = idx >> 5, q = idx & 31;
            *(float4*)(sm + r * GSTRIDE + 4 * q) =
                *(const float4*)(base + (size_t)r * DDIM + ch * 128 + 4 * q);
        }
        __syncthreads();

        const float* pa = sm + (3 * tr) * GSTRIDE;
        const float* pb = sm + (3 * tc) * GSTRIDE;
        #pragma unroll 8
        for (int q = 0; q < 32; ++q) {
            float4 a0 = *(const float4*)(pa + 4 * q);
            float4 a1 = *(const float4*)(pa + GSTRIDE + 4 * q);
            float4 a2 = *(const float4*)(pa + 2 * GSTRIDE + 4 * q);
            float4 b0 = *(const float4*)(pb + 4 * q);
            float4 b1 = *(const float4*)(pb + GSTRIDE + 4 * q);
            float4 b2 = *(const float4*)(pb + 2 * GSTRIDE + 4 * q);
            acc[0][0] += a0.x * b0.x + a0.y * b0.y + a0.z * b0.z + a0.w * b0.w;
            acc[0][1] += a0.x * b1.x + a0.y * b1.y + a0.z * b1.z + a0.w * b1.w;
            acc[0][2] += a0.x * b2.x + a0.y * b2.y + a0.z * b2.z + a0.w * b2.w;
            acc[1][0] += a1.x * b0.x + a1.y * b0.y + a1.z * b0.z + a1.w * b0.w;
            acc[1][1] += a1.x * b1.x + a1.y * b1.y + a1.z * b1.z + a1.w * b1.w;
            acc[1][2] += a1.x * b2.x + a1.y * b2.y + a1.z * b2.z + a1.w * b2.w;
            acc[2][0] += a2.x * b0.x + a2.y * b0.y + a2.z * b0.z + a2.w * b0.w;
            acc[2][1] += a2.x * b1.x + a2.y * b1.y + a2.z * b1.z + a2.w * b1.w;
            acc[2][2] += a2.x * b2.x + a2.y * b2.y + a2.z * b2.z + a2.w * b2.w;
        }
    }

    #pragma unroll
    for (int ka = 0; ka < 3; ++ka)
        #pragma unroll
        for (int kb = 0; kb < 3; ++kb) {
            int r1 = 3 * tr + ka, r2 = 3 * tc + kb;
            if (r1 <= r2)
                g_tri[i * TRI_LEN + c_OFF[r1] + (r2 - r1)] = acc[ka][kb];
        }
}

// ============================================================================
// HMMA GEMM (pure fp16) with caption-length masking.
// 2-stage pipeline, ONE barrier per chunk, 3 CTAs/SM.
//   iter c: wait_group(0); sync; load(c+1); compute(c)
// The barrier both publishes stage c and frees stage (c+1)%2 for reload.
// ============================================================================
#define ROWB 144
#define TEN_BYTES (128 * ROWB)
#define STAGE_BYTES (2 * TEN_BYTES)
#define NSTAGES 2
#define NCHUNK 16

__global__ void __launch_bounds__(256, 3) gemm_hmma(const int* __restrict__ s_l) {
    extern __shared__ __align__(128) unsigned char dsm[];
    const int tid = threadIdx.x, wid = tid >> 5, lane = tid & 31;
    const int bx = blockIdx.x;
    const int by = blockIdx.y;
    const int wm = (wid & 3) * 32, wn = (wid >> 2) * 64;
    const int g = lane >> 2, tig = lane & 3;
    const unsigned sbase = su32(dsm);

    const int L0 = s_l[bx * 2], L1 = s_l[bx * 2 + 1];
    const int Lw = (wid >> 2) ? L1 : L0;
    const int nk8 = (Lw + 7) >> 3;
    const int nk16 = (nk8 + 1) >> 1;
    const int keep0 = (L0 + 7) & ~7, keep1 = (L1 + 7) & ~7;

    const unsigned a_off = (unsigned)((lane & 15) * ROWB + ((lane >> 4) << 4));
    const unsigned b_off = (unsigned)(((lane & 7) + ((lane >> 4) << 3)) * ROWB
                                      + (((lane >> 3) & 1) << 4));

    const char* gA = (const char*)g_A + (size_t)by * 128 * 2048;
    const char* gB = (const char*)g_B + (size_t)bx * 128 * 2048;

    float acc[2][8][4];
    #pragma unroll
    for (int mt = 0; mt < 2; ++mt)
        #pragma unroll
        for (int nt = 0; nt < 8; ++nt)
            #pragma unroll
            for (int q = 0; q < 4; ++q) acc[mt][nt][q] = 0.f;

    auto load_stage = [&](int c) {
        const unsigned tb = sbase + (unsigned)(c & 1) * STAGE_BYTES;
        const int kb = c * 128;
        #pragma unroll
        for (int it = 0; it < 8; ++it) {
            int idx = it * 256 + tid;
            int ten = idx >> 10;
            int rem = idx & 1023;
            int row = rem >> 3, q = rem & 7;
            if (ten == 0) {
                cpa16_s(tb + row * ROWB + q * 16,
                        gA + (size_t)row * 2048 + kb + q * 16);
            } else {
                int word = row & 63;
                int keep = (row >> 6) ? keep1 : keep0;
                if (word < keep)
                    cpa16_s(tb + TEN_BYTES + row * ROWB + q * 16,
                            gB + (size_t)row * 2048 + kb + q * 16);
            }
        }
        cp_commit();
    };

    load_stage(0);

    for (int c = 0; c < NCHUNK; ++c) {
        asm volatile("cp.async.wait_group 0;" ::: "memory");
        __syncthreads();                 // publishes stage c; frees stage (c+1)&1

        if (c + 1 < NCHUNK) load_stage(c + 1);   // overlaps compute(c)

        const unsigned tb = sbase + (unsigned)(c & 1) * STAGE_BYTES;
        const unsigned As = tb + (unsigned)(wm * ROWB) + a_off;
        const unsigned Bs = tb + TEN_BYTES + (unsigned)(wn * ROWB) + b_off;

        #pragma unroll
        for (int kk = 0; kk < 4; ++kk) {
            const unsigned kb = (unsigned)(kk * 32);

            unsigned a[2][4];
            #pragma unroll
            for (int mt = 0; mt < 2; ++mt)
                LDSM4(a[mt], As + (unsigned)(mt * 16 * ROWB) + kb);

            #pragma unroll
            for (int nbp = 0; nbp < 4; ++nbp) {
                if (nbp < nk16) {                    // warp-uniform
                    unsigned b[4];
                    LDSM4(b, Bs + (unsigned)(nbp * 16 * ROWB) + kb);
                    #pragma unroll
                    for (int mt = 0; mt < 2; ++mt)
                        MMAF16(acc[mt][2 * nbp + 0], a[mt], b[0], b[1]);
                    if (2 * nbp + 1 < nk8) {         // warp-uniform
                        #pragma unroll
                        for (int mt = 0; mt < 2; ++mt)
                            MMAF16(acc[mt][2 * nbp + 1], a[mt], b[2], b[3]);
                    }
                }
            }
        }
    }

    float* cbase = g_C + (size_t)(by * 128 + wm) * 8192 + bx * 128 + wn;
    #pragma unroll
    for (int mt = 0; mt < 2; ++mt)
        #pragma unroll
        for (int nb = 0; nb < 8; ++nb) {
            if (nb < nk8) {
                float* p0 = cbase + (size_t)(mt * 16 + g) * 8192 + nb * 8 + 2 * tig;
                *(float2*)p0 = make_float2(acc[mt][nb][0], acc[mt][nb][1]);
                *(float2*)(p0 + 8 * 8192) = make_float2(acc[mt][nb][2], acc[mt][nb][3]);
            }
        }
}

// ============================================================================
// Per-pair epilogue -> scores[i][j], 4 captions per CTA.
// ============================================================================
#define A0STRIDE 68

__global__ void __launch_bounds__(256, 3) scores_kernel(const int* __restrict__ s_l) {
    __shared__ float A0s[4][RDIM * A0STRIDE];
    __shared__ __align__(16) float Gs[TRI_LEN];
    __shared__ float rn [4][RDIM];
    __shared__ float part[4][2];

    const int tid = threadIdx.x;
    const int grp = tid >> 6, wt = tid & 63;
    const int j = blockIdx.x * 4 + grp;
    const int i = blockIdx.y;
    const int L = s_l[j];

    const float4* pc4 = (const float4*)(g_C + (size_t)(i * RDIM) * 8192 + j * 64);
    #pragma unroll
    for (int idx = wt; idx < RDIM * 16; idx += 64) {
        int r = idx >> 4, q = idx & 15;
        *(float4*)(A0s[grp] + r * A0STRIDE + 4 * q) = pc4[(size_t)r * 2048 + q];
    }
    const float4* pg4 = (const float4*)(g_tri + i * TRI_LEN);
    for (int idx = tid; idx < TRI_LEN / 4; idx += 256)
        ((float4*)Gs)[idx] = pg4[idx];
    __syncthreads();

    if (wt < RDIM) {
        float sum = 0.f;
        const float* row = A0s[grp] + wt * A0STRIDE;
        for (int w2 = 0; w2 < L; ++w2) {
            float x = row[w2];
            x = (x > 0.f) ? x : 0.1f * x;
            sum += x * x;
        }
        rn[grp][wt] = 9.0f / (sqrtf(sum) + 1e-8f);
    }
    __syncthreads();

    float t = 0.f;
    if (wt < L) {
        const int w = wt;
        float e[RDIM + 4];
        float m = -1e30f;
        #pragma unroll
        for (int r = 0; r < RDIM; ++r) {
            float x = A0s[grp][r * A0STRIDE + w];
            x = (x > 0.f) ? x : 0.1f * x;
            x *= rn[grp][r];
            e[r] = x;
            m = fmaxf(m, x);
        }
        #pragma unroll
        for (int r = RDIM; r < RDIM + 4; ++r) e[r] = 0.f;
        float se = 0.f, num = 0.f;
        #pragma unroll
        for (int r = 0; r < RDIM; ++r) {
            float ev = __expf(e[r] - m);
            e[r] = ev;
            se += ev;
            num += ev * A0s[grp][r * A0STRIDE + w];
        }
        float quad = 0.f;
        #pragma unroll
        for (int r = 0; r < RDIM; ++r) {
            const int off = c_OFF[r];
            const int nq = (39 - r) >> 2;
            const float4* gr = (const float4*)(Gs + off);
            float v = 0.f;
            #pragma unroll
            for (int q = 0; q < nq; ++q) {
                float4 gv = gr[q];
                v += gv.x * e[r + 4 * q] + gv.y * e[r + 4 * q + 1]
                   + gv.z * e[r + 4 * q + 2] + gv.w * e[r + 4 * q + 3];
            }
            quad += e[r] * (2.f * v - Gs[off] * e[r]);
        }
        quad = fmaxf(quad, 0.f);
        float nwei  = sqrtf(quad) / se;
        float numn  = num / se;
        float ncv   = g_ncap[j * WDIM + w];
        float denom = fmaxf(ncv * nwei, 1e-8f);
        float rowv  = numn / denom;
        t = __expf(6.0f * rowv);
    }
    #pragma unroll
    for (int o = 16; o; o >>= 1) t += __shfl_down_sync(0xffffffffu, t, o);
    if ((wt & 31) == 0) part[grp][wt >> 5] = t;
    __syncthreads();
    if (wt == 0) g_scores[i * BDIM + j] = logf(part[grp][0] + part[grp][1]) / 6.0f;
}

// ============================================================================
// Hardest-negative hinge loss
// ============================================================================
__global__ void __launch_bounds__(128) loss_kernel(float* __restrict__ out) {
    __shared__ float red[128];
    const int t = threadIdx.x;
    const float di = g_scores[t * BDIM + t];
    float ms = 0.f, mi = 0.f;
    for (int k = 0; k < BDIM; ++k) {
        if (k == t) continue;
        ms = fmaxf(ms, fmaxf(0.f, 0.2f + g_scores[t * BDIM + k] - di));
        mi = fmaxf(mi, fmaxf(0.f, 0.2f + g_scores[k * BDIM + t] - di));
    }
    red[t] = ms + mi;
    __syncthreads();
    for (int st = 64; st > 0; st >>= 1) {
        if (t < st) red[t] += red[t + st];
        __syncthreads();
    }
    if (t == 0) out[0] = red[0];
}

// ============================================================================
extern "C" void kernel_launch(void* const* d_in, const int* in_sizes, int n_in,
                              void* d_out, int out_size) {
    const float* im = (const float*)d_in[0];
    const float* s  = (const float*)d_in[1];
    const int*   sl = (const int*)d_in[2];
    float* out = (float*)d_out;

    cudaFuncSetAttribute(gemm_hmma, cudaFuncAttributeMaxDynamicSharedMemorySize,
                         NSTAGES * STAGE_BYTES);

    convert_im_kernel<<<(BDIM * RDIM * DDIM / 4 + 255) / 256, 256>>>(im);
    convs_ncap_kernel<<<BDIM * WDIM, 256>>>(s);
    gram_kernel<<<BDIM, 144>>>(im);
    gemm_hmma<<<dim3(64, 36), 256, NSTAGES * STAGE_BYTES>>>(sl);
    scores_kernel<<<dim3(BDIM / 4, BDIM), 256>>>(sl);
    loss_kernel<<<1, 128>>>(out);
}

// round 16
// speedup vs baseline: 1.4277x; 1.4277x over previous
#include <cuda_runtime.h>
#include <cuda_fp16.h>
#include <cstdint>
#include <math.h>

#define BDIM 128
#define RDIM 36
#define WDIM 64
#define DDIM 1024
#define TRI_LEN 720   // packed padded upper-triangular Gram floats per image

// ---------------- device globals (no runtime allocation; zero-initialized) --
__device__ __align__(128) float g_C[(size_t)BDIM * RDIM * BDIM * WDIM];   // [4608][8192]
__device__ __align__(128) __half g_A[(size_t)BDIM * RDIM * DDIM];         // fp16(im)
__device__ __align__(128) __half g_B[(size_t)BDIM * WDIM * DDIM];         // fp16(s)
__device__ __align__(16) float g_tri[BDIM * TRI_LEN];                      // packed Gram
__device__ float g_ncap[BDIM * WDIM];
__device__ float g_scores[BDIM * BDIM];

// row r of the packed triangular Gram starts at OFF[r], width ((39-r)&~3)
__constant__ int c_OFF[RDIM] = {
    0, 36, 72, 108, 144, 176, 208, 240, 272, 300, 328, 356,
    384, 408, 432, 456, 480, 500, 520, 540, 560, 576, 592, 608,
    624, 636, 648, 660, 672, 680, 688, 696, 704, 708, 712, 716};

// ---------------- PTX helpers (baseline compute_103-safe only) ----------------
__device__ __forceinline__ unsigned su32(const void* p) {
    unsigned a;
    asm("{ .reg .u64 t; cvta.to.shared.u64 t, %1; cvt.u32.u64 %0, t; }" : "=r"(a) : "l"(p));
    return a;
}
__device__ __forceinline__ void cpa16_s(unsigned dst, const void* src) {
    asm volatile("cp.async.cg.shared.global [%0], [%1], 16;" :: "r"(dst), "l"(src));
}
__device__ __forceinline__ void cp_commit() { asm volatile("cp.async.commit_group;"); }

#define LDSM4(r, addr) \
    asm volatile("ldmatrix.sync.aligned.m8n8.x4.shared.b16 {%0,%1,%2,%3}, [%4];" \
                 : "=r"((r)[0]), "=r"((r)[1]), "=r"((r)[2]), "=r"((r)[3]) : "r"(addr))

#define MMAF16(d, a, b0v, b1v) \
    asm volatile("mma.sync.aligned.m16n8k16.row.col.f32.f16.f16.f32 " \
                 "{%0,%1,%2,%3}, {%4,%5,%6,%7}, {%8,%9}, {%0,%1,%2,%3};" \
                 : "+f"((d)[0]), "+f"((d)[1]), "+f"((d)[2]), "+f"((d)[3]) \
                 : "r"((a)[0]), "r"((a)[1]), "r"((a)[2]), "r"((a)[3]), "r"(b0v), "r"(b1v))

// ============================================================================
// Converts. Device globals referenced DIRECTLY in device code (host-side
// symbol decay -> host shadow; GB300 ATS accepts it silently).
// ============================================================================
__global__ void __launch_bounds__(256) convert_im_kernel(const float* __restrict__ im) {
    int i = blockIdx.x * 256 + threadIdx.x;                 // over float4s
    if (i >= BDIM * RDIM * DDIM / 4) return;
    float4 x = ((const float4*)im)[i];
    __half2* ap = (__half2*)g_A;
    ap[2 * i]     = __half2(__float2half_rn(x.x), __float2half_rn(x.y));
    ap[2 * i + 1] = __half2(__float2half_rn(x.z), __float2half_rn(x.w));
}

// convert_s merged with ncap: one block per caption-word row (8192 rows)
__global__ void __launch_bounds__(256) convs_ncap_kernel(const float* __restrict__ s) {
    const int row = blockIdx.x;            // 0..8191
    const int t = threadIdx.x;
    const int warp = t >> 5, lane = t & 31;
    __shared__ float ws[8];

    float4 x = ((const float4*)(s + (size_t)row * DDIM))[t];
    __half2* bp = (__half2*)(g_B + (size_t)row * DDIM);
    bp[2 * t]     = __half2(__float2half_rn(x.x), __float2half_rn(x.y));
    bp[2 * t + 1] = __half2(__float2half_rn(x.z), __float2half_rn(x.w));

    float ss = x.x * x.x + x.y * x.y + x.z * x.z + x.w * x.w;
    #pragma unroll
    for (int o = 16; o; o >>= 1) ss += __shfl_down_sync(0xffffffffu, ss, o);
    if (lane == 0) ws[warp] = ss;
    __syncthreads();
    if (t == 0) {
        float tot = 0.f;
        #pragma unroll
        for (int k = 0; k < 8; ++k) tot += ws[k];
        g_ncap[row] = sqrtf(tot);
    }
}

// ============================================================================
// Gram: register-blocked tiled kernel (one CTA per image, 144 threads).
// ============================================================================
#define GSTRIDE 132

__global__ void __launch_bounds__(144) gram_kernel(const float* __restrict__ im) {
    __shared__ __align__(16) float sm[RDIM * GSTRIDE];
    const int i = blockIdx.x;
    const int t = threadIdx.x;
    const int tr = t / 12, tc = t - tr * 12;
    const float* base = im + (size_t)i * RDIM * DDIM;

    for (int idx = t; idx < TRI_LEN; idx += 144) g_tri[i * TRI_LEN + idx] = 0.f;

    float acc[3][3];
    #pragma unroll
    for (int ka = 0; ka < 3; ++ka)
        #pragma unroll
        for (int kb = 0; kb < 3; ++kb) acc[ka][kb] = 0.f;

    for (int ch = 0; ch < 8; ++ch) {
        __syncthreads();
        for (int idx = t; idx < RDIM * 32; idx += 144) {
            int r = idx >> 5, q = idx & 31;
            *(float4*)(sm + r * GSTRIDE + 4 * q) =
                *(const float4*)(base + (size_t)r * DDIM + ch * 128 + 4 * q);
        }
        __syncthreads();

        const float* pa = sm + (3 * tr) * GSTRIDE;
        const float* pb = sm + (3 * tc) * GSTRIDE;
        #pragma unroll 8
        for (int q = 0; q < 32; ++q) {
            float4 a0 = *(const float4*)(pa + 4 * q);
            float4 a1 = *(const float4*)(pa + GSTRIDE + 4 * q);
            float4 a2 = *(const float4*)(pa + 2 * GSTRIDE + 4 * q);
            float4 b0 = *(const float4*)(pb + 4 * q);
            float4 b1 = *(const float4*)(pb + GSTRIDE + 4 * q);
            float4 b2 = *(const float4*)(pb + 2 * GSTRIDE + 4 * q);
            acc[0][0] += a0.x * b0.x + a0.y * b0.y + a0.z * b0.z + a0.w * b0.w;
            acc[0][1] += a0.x * b1.x + a0.y * b1.y + a0.z * b1.z + a0.w * b1.w;
            acc[0][2] += a0.x * b2.x + a0.y * b2.y + a0.z * b2.z + a0.w * b2.w;
            acc[1][0] += a1.x * b0.x + a1.y * b0.y + a1.z * b0.z + a1.w * b0.w;
            acc[1][1] += a1.x * b1.x + a1.y * b1.y + a1.z * b1.z + a1.w * b1.w;
            acc[1][2] += a1.x * b2.x + a1.y * b2.y + a1.z * b2.z + a1.w * b2.w;
            acc[2][0] += a2.x * b0.x + a2.y * b0.y + a2.z * b0.z + a2.w * b0.w;
            acc[2][1] += a2.x * b1.x + a2.y * b1.y + a2.z * b1.z + a2.w * b1.w;
            acc[2][2] += a2.x * b2.x + a2.y * b2.y + a2.z * b2.z + a2.w * b2.w;
        }
    }

    #pragma unroll
    for (int ka = 0; ka < 3; ++ka)
        #pragma unroll
        for (int kb = 0; kb < 3; ++kb) {
            int r1 = 3 * tr + ka, r2 = 3 * tc + kb;
            if (r1 <= r2)
                g_tri[i * TRI_LEN + c_OFF[r1] + (r2 - r1)] = acc[ka][kb];
        }
}

// ============================================================================
// HMMA GEMM (pure fp16) with caption-length masking.
// 3-stage pipeline, 2 CTAs/SM (regs 114 — no spills), ONE barrier per chunk:
//   iter c: wait_group(1); sync; load(c+2); compute(c)
// Barrier at iter c proves compute(c-1) done in all warps -> stage (c+2)%3
// (== (c-1)%3) is free to reload. wait_group(1) proves stage c landed.
// ============================================================================
#define ROWB 144
#define TEN_BYTES (128 * ROWB)
#define STAGE_BYTES (2 * TEN_BYTES)
#define NSTAGES 3
#define NCHUNK 16

__global__ void __launch_bounds__(256, 2) gemm_hmma(const int* __restrict__ s_l) {
    extern __shared__ __align__(128) unsigned char dsm[];
    const int tid = threadIdx.x, wid = tid >> 5, lane = tid & 31;
    const int bx = blockIdx.x;
    const int by = blockIdx.y;
    const int wm = (wid & 3) * 32, wn = (wid >> 2) * 64;
    const int g = lane >> 2, tig = lane & 3;
    const unsigned sbase = su32(dsm);

    const int L0 = s_l[bx * 2], L1 = s_l[bx * 2 + 1];
    const int Lw = (wid >> 2) ? L1 : L0;
    const int nk8 = (Lw + 7) >> 3;
    const int nk16 = (nk8 + 1) >> 1;
    const int keep0 = (L0 + 7) & ~7, keep1 = (L1 + 7) & ~7;

    const unsigned a_off = (unsigned)((lane & 15) * ROWB + ((lane >> 4) << 4));
    const unsigned b_off = (unsigned)(((lane & 7) + ((lane >> 4) << 3)) * ROWB
                                      + (((lane >> 3) & 1) << 4));

    const char* gA = (const char*)g_A + (size_t)by * 128 * 2048;
    const char* gB = (const char*)g_B + (size_t)bx * 128 * 2048;

    float acc[2][8][4];
    #pragma unroll
    for (int mt = 0; mt < 2; ++mt)
        #pragma unroll
        for (int nt = 0; nt < 8; ++nt)
            #pragma unroll
            for (int q = 0; q < 4; ++q) acc[mt][nt][q] = 0.f;

    auto load_stage = [&](int c) {
        const unsigned tb = sbase + (unsigned)(c % NSTAGES) * STAGE_BYTES;
        const int kb = c * 128;
        #pragma unroll
        for (int it = 0; it < 8; ++it) {
            int idx = it * 256 + tid;
            int ten = idx >> 10;
            int rem = idx & 1023;
            int row = rem >> 3, q = rem & 7;
            if (ten == 0) {
                cpa16_s(tb + row * ROWB + q * 16,
                        gA + (size_t)row * 2048 + kb + q * 16);
            } else {
                int word = row & 63;
                int keep = (row >> 6) ? keep1 : keep0;
                if (word < keep)
                    cpa16_s(tb + TEN_BYTES + row * ROWB + q * 16,
                            gB + (size_t)row * 2048 + kb + q * 16);
            }
        }
        cp_commit();
    };

    load_stage(0);
    load_stage(1);

    for (int c = 0; c < NCHUNK; ++c) {
        asm volatile("cp.async.wait_group 1;" ::: "memory");   // stage c landed
        __syncthreads();   // all warps done with compute(c-1); frees stage (c+2)%3

        if (c + 2 < NCHUNK) load_stage(c + 2);   // overlaps compute(c)
        else cp_commit();                        // keep group accounting uniform

        const unsigned tb = sbase + (unsigned)(c % NSTAGES) * STAGE_BYTES;
        const unsigned As = tb + (unsigned)(wm * ROWB) + a_off;
        const unsigned Bs = tb + TEN_BYTES + (unsigned)(wn * ROWB) + b_off;

        #pragma unroll
        for (int kk = 0; kk < 4; ++kk) {
            const unsigned kb = (unsigned)(kk * 32);

            unsigned a[2][4];
            #pragma unroll
            for (int mt = 0; mt < 2; ++mt)
                LDSM4(a[mt], As + (unsigned)(mt * 16 * ROWB) + kb);

            #pragma unroll
            for (int nbp = 0; nbp < 4; ++nbp) {
                if (nbp < nk16) {                    // warp-uniform
                    unsigned b[4];
                    LDSM4(b, Bs + (unsigned)(nbp * 16 * ROWB) + kb);
                    #pragma unroll
                    for (int mt = 0; mt < 2; ++mt)
                        MMAF16(acc[mt][2 * nbp + 0], a[mt], b[0], b[1]);
                    if (2 * nbp + 1 < nk8) {         // warp-uniform
                        #pragma unroll
                        for (int mt = 0; mt < 2; ++mt)
                            MMAF16(acc[mt][2 * nbp + 1], a[mt], b[2], b[3]);
                    }
                }
            }
        }
    }

    float* cbase = g_C + (size_t)(by * 128 + wm) * 8192 + bx * 128 + wn;
    #pragma unroll
    for (int mt = 0; mt < 2; ++mt)
        #pragma unroll
        for (int nb = 0; nb < 8; ++nb) {
            if (nb < nk8) {
                float* p0 = cbase + (size_t)(mt * 16 + g) * 8192 + nb * 8 + 2 * tig;
                *(float2*)p0 = make_float2(acc[mt][nb][0], acc[mt][nb][1]);
                *(float2*)(p0 + 8 * 8192) = make_float2(acc[mt][nb][2], acc[mt][nb][3]);
            }
        }
}

// ============================================================================
// Per-pair epilogue -> scores[i][j], 4 captions per CTA.
// ============================================================================
#define A0STRIDE 68

__global__ void __launch_bounds__(256, 3) scores_kernel(const int* __restrict__ s_l) {
    __shared__ float A0s[4][RDIM * A0STRIDE];
    __shared__ __align__(16) float Gs[TRI_LEN];
    __shared__ float rn [4][RDIM];
    __shared__ float part[4][2];

    const int tid = threadIdx.x;
    const int grp = tid >> 6, wt = tid & 63;
    const int j = blockIdx.x * 4 + grp;
    const int i = blockIdx.y;
    const int L = s_l[j];

    const float4* pc4 = (const float4*)(g_C + (size_t)(i * RDIM) * 8192 + j * 64);
    #pragma unroll
    for (int idx = wt; idx < RDIM * 16; idx += 64) {
        int r = idx >> 4, q = idx & 15;
        *(float4*)(A0s[grp] + r * A0STRIDE + 4 * q) = pc4[(size_t)r * 2048 + q];
    }
    const float4* pg4 = (const float4*)(g_tri + i * TRI_LEN);
    for (int idx = tid; idx < TRI_LEN / 4; idx += 256)
        ((float4*)Gs)[idx] = pg4[idx];
    __syncthreads();

    if (wt < RDIM) {
        float sum = 0.f;
        const float* row = A0s[grp] + wt * A0STRIDE;
        for (int w2 = 0; w2 < L; ++w2) {
            float x = row[w2];
            x = (x > 0.f) ? x : 0.1f * x;
            sum += x * x;
        }
        rn[grp][wt] = 9.0f / (sqrtf(sum) + 1e-8f);
    }
    __syncthreads();

    float t = 0.f;
    if (wt < L) {
        const int w = wt;
        float e[RDIM + 4];
        float m = -1e30f;
        #pragma unroll
        for (int r = 0; r < RDIM; ++r) {
            float x = A0s[grp][r * A0STRIDE + w];
            x = (x > 0.f) ? x : 0.1f * x;
            x *= rn[grp][r];
            e[r] = x;
            m = fmaxf(m, x);
        }
        #pragma unroll
        for (int r = RDIM; r < RDIM + 4; ++r) e[r] = 0.f;
        float se = 0.f, num = 0.f;
        #pragma unroll
        for (int r = 0; r < RDIM; ++r) {
            float ev = __expf(e[r] - m);
            e[r] = ev;
            se += ev;
            num += ev * A0s[grp][r * A0STRIDE + w];
        }
        float quad = 0.f;
        #pragma unroll
        for (int r = 0; r < RDIM; ++r) {
            const int off = c_OFF[r];
            const int nq = (39 - r) >> 2;
            const float4* gr = (const float4*)(Gs + off);
            float v = 0.f;
            #pragma unroll
            for (int q = 0; q < nq; ++q) {
                float4 gv = gr[q];
                v += gv.x * e[r + 4 * q] + gv.y * e[r + 4 * q + 1]
                   + gv.z * e[r + 4 * q + 2] + gv.w * e[r + 4 * q + 3];
            }
            quad += e[r] * (2.f * v - Gs[off] * e[r]);
        }
        quad = fmaxf(quad, 0.f);
        float nwei  = sqrtf(quad) / se;
        float numn  = num / se;
        float ncv   = g_ncap[j * WDIM + w];
        float denom = fmaxf(ncv * nwei, 1e-8f);
        float rowv  = numn / denom;
        t = __expf(6.0f * rowv);
    }
    #pragma unroll
    for (int o = 16; o; o >>= 1) t += __shfl_down_sync(0xffffffffu, t, o);
    if ((wt & 31) == 0) part[grp][wt >> 5] = t;
    __syncthreads();
    if (wt == 0) g_scores[i * BDIM + j] = logf(part[grp][0] + part[grp][1]) / 6.0f;
}

// ============================================================================
// Hardest-negative hinge loss
// ============================================================================
__global__ void __launch_bounds__(128) loss_kernel(float* __restrict__ out) {
    __shared__ float red[128];
    const int t = threadIdx.x;
    const float di = g_scores[t * BDIM + t];
    float ms = 0.f, mi = 0.f;
    for (int k = 0; k < BDIM; ++k) {
        if (k == t) continue;
        ms = fmaxf(ms, fmaxf(0.f, 0.2f + g_scores[t * BDIM + k] - di));
        mi = fmaxf(mi, fmaxf(0.f, 0.2f + g_scores[k * BDIM + t] - di));
    }
    red[t] = ms + mi;
    __syncthreads();
    for (int st = 64; st > 0; st >>= 1) {
        if (t < st) red[t] += red[t + st];
        __syncthreads();
    }
    if (t == 0) out[0] = red[0];
}

// ============================================================================
extern "C" void kernel_launch(void* const* d_in, const int* in_sizes, int n_in,
                              void* d_out, int out_size) {
    const float* im = (const float*)d_in[0];
    const float* s  = (const float*)d_in[1];
    const int*   sl = (const int*)d_in[2];
    float* out = (float*)d_out;

    cudaFuncSetAttribute(gemm_hmma, cudaFuncAttributeMaxDynamicSharedMemorySize,
                         NSTAGES * STAGE_BYTES);

    convert_im_kernel<<<(BDIM * RDIM * DDIM / 4 + 255) / 256, 256>>>(im);
    convs_ncap_kernel<<<BDIM * WDIM, 256>>>(s);
    gram_kernel<<<BDIM, 144>>>(im);
    gemm_hmma<<<dim3(64, 36), 256, NSTAGES * STAGE_BYTES>>>(sl);
    scores_kernel<<<dim3(BDIM / 4, BDIM), 256>>>(sl);
    loss_kernel<<<1, 128>>>(out);
}